// round 14
// baseline (speedup 1.0000x reference)
#include <cuda_runtime.h>
#include <cuda_fp16.h>

#define NSEG   128
#define SDIM   32
#define TDIM   32
#define NWARPS 4
#define NTHREADS 128
#define SPLIT  12
#define NBINS  34                 // bin = r+1, r in [-1, 32]
#define PITCH  32                 // word addr = 32*bin + t  ->  bank = t (conflict-free)

__device__ int      g_bounds[NSEG + 1];
__device__ float    g_scratch[NSEG * SDIM * TDIM];   // zero-init; self-cleaned
__device__ unsigned g_count[NSEG];                   // zero-init; self-cleaned

__device__ __forceinline__ long long ld_idx(const void* p, int i, bool is64) {
    return is64 ? ((const long long*)p)[i] : (long long)((const int*)p)[i];
}

// prep: segment boundaries only, 4 entries/thread flat scan (no dependent loads)
__global__ void __launch_bounds__(256)
prep_kernel(const void* __restrict__ idxraw, int N)
{
    const int gtid = blockIdx.x * blockDim.x + threadIdx.x;
    const bool is64 = (((const int*)idxraw)[(N - 2) | 1] == 0);

    const int base = gtid * 4;
    if (base >= N) return;
    int vals[5];
    if (is64) {
        const longlong2* p = (const longlong2*)idxraw;
        longlong2 a = __ldg(p + (base >> 1));
        longlong2 b = (base + 2 < N) ? __ldg(p + (base >> 1) + 1)
                                     : make_longlong2(0, 0);
        vals[0] = (int)a.x; vals[1] = (int)a.y;
        vals[2] = (int)b.x; vals[3] = (int)b.y;
    } else {
        int4 a = __ldg((const int4*)idxraw + (base >> 2));
        vals[0] = a.x; vals[1] = a.y; vals[2] = a.z; vals[3] = a.w;
    }
    vals[4] = (base + 4 < N) ? (int)ld_idx(idxraw, base + 4, is64) : NSEG;

    if (base == 0)
        for (int j = 0; j <= vals[0]; j++) g_bounds[j] = 0;
    #pragma unroll
    for (int k = 0; k < 4; k++) {
        int i = base + k;
        if (i < N) {
            int a = vals[k];
            int b = (i == N - 1) ? NSEG : vals[k + 1];
            for (int j = a + 1; j <= b; j++) g_bounds[j] = i + 1;
        }
    }
}

__global__ void __launch_bounds__(NTHREADS, SPLIT)
ect_kernel(const float* __restrict__ x, const float* __restrict__ v,
           const float* __restrict__ lin, const void* __restrict__ scaleraw,
           float* __restrict__ out)
{
    // per-warp accumulators: half2 {count, tanh-sum} per (bin, t)  (4.25 KB/warp)
    __shared__ __half2 acc[NWARPS][NBINS * PITCH];
    __shared__ float   tw[NWARPS][TDIM];
    __shared__ int     islast;

    const int tid = threadIdx.x;
    const int w   = tid >> 5;
    const int t   = tid & 31;
    const int seg  = (int)blockIdx.x / SPLIT;
    const int part = (int)blockIdx.x - seg * SPLIT;

    // zero accumulators, 16B-vectorized
    {
        int4* z = (int4*)&acc[0][0];
        const int n16 = (NWARPS * NBINS * PITCH) / 4;
        for (int i = tid; i < n16; i += NTHREADS)
            z[i] = make_int4(0, 0, 0, 0);
    }

    const int segS = g_bounds[seg];
    const int segE = g_bounds[seg + 1];

    // scale: int32/int64 low word, or float32
    int s_i = *(const int*)scaleraw;
    const float scale = (s_i > 0 && s_i < 1000000) ? (float)s_i
                                                   : *(const float*)scaleraw;

    const float lin0   = lin[0];
    const float dl     = (lin[SDIM - 1] - lin0) * (1.0f / (SDIM - 1));
    const float inv_dl = 1.0f / dl;
    const float K2     = -0.5f * scale * dl;      // tanh arg scale
    const float nb     = -lin0 * inv_dl;
    const float MAGIC  = 12582912.0f;             // 2^23 + 2^22
    const unsigned MAGICI = 0x4B400000u;
    const float K2M    = K2 * MAGIC;

    // fold inv_dl into the projection: u = x . (v*inv_dl) + nb
    const float v0 = v[t] * inv_dl;
    const float v1 = v[TDIM + t] * inv_dl;
    const float v2 = v[2 * TDIM + t] * inv_dl;

    // bin -> smem byte address in ONE IMAD: off = bits(u+MAGIC)*128 + adj
    const unsigned sbase = (unsigned)__cvta_generic_to_shared(&acc[0][0]);
    const unsigned adj   = sbase + (unsigned)(w * NBINS * PITCH * 4)
                         + (unsigned)(t * 4) + 128u - MAGICI * 128u;  // mod 2^32

    const int chunk = (segE - segS + SPLIT - 1) / SPLIT;
    int start = segS + part * chunk;
    if (start > segE) start = segE;
    int end = start + chunk;
    if (end > segE) end = segE;

    int gs = (start + 3) & ~3;                    // first float4-aligned node
    if (gs > end) gs = end;
    const int ge = gs + ((end - gs) & ~3);

    // serial per-node RMW (LSU pipelines distinct-addr RMWs)
    auto proc = [&](float u) {
        u = fminf(fmaxf(u, -0.6f), 32.4f);
        float f = u + MAGIC;                       // rint via magic number
        float t1 = fmaf(f, -K2, K2M);              // = -K2*rint(u)
        float z  = fmaf(u, K2, t1);                // = K2*(u - rint(u))
        float th; asm("tanh.approx.f32 %0, %1;" : "=f"(th) : "f"(z));
        __half2 inc = __floats2half2_rn(1.0f, th); // {count, tanh}
        unsigned incu = *reinterpret_cast<unsigned*>(&inc);
        unsigned off = __float_as_uint(f) * 128u + adj;   // single IMAD
        unsigned cur;
        asm volatile("ld.shared.b32 %0, [%1];" : "=r"(cur) : "r"(off));
        __half2 ch = *reinterpret_cast<__half2*>(&cur);
        __half2 ih = *reinterpret_cast<__half2*>(&incu);
        ch = __hadd2(ch, ih);
        unsigned res = *reinterpret_cast<unsigned*>(&ch);
        asm volatile("st.shared.b32 [%0], %1;" :: "r"(off), "r"(res));
    };

    // main loop: 4 nodes/iter, 3x float4 broadcast loads
    for (int n = gs + w * 4; n < ge; n += NWARPS * 4) {
        const float4* xp = (const float4*)(x + 3 * n);
        float4 A = __ldg(xp), B = __ldg(xp + 1), C = __ldg(xp + 2);
        float u0 = fmaf(A.z, v2, fmaf(A.y, v1, fmaf(A.x, v0, nb)));
        float u1 = fmaf(B.y, v2, fmaf(B.x, v1, fmaf(A.w, v0, nb)));
        float u2 = fmaf(C.x, v2, fmaf(B.w, v1, fmaf(B.z, v0, nb)));
        float u3 = fmaf(C.w, v2, fmaf(C.z, v1, fmaf(C.y, v0, nb)));
        proc(u0); proc(u1); proc(u2); proc(u3);
    }
    // scalar remainders (<= 3 each side), warp 0
    if (w == 0) {
        for (int n = start; n < gs; n++) {
            const float* xp = x + 3 * n;
            proc(fmaf(__ldg(xp + 2), v2, fmaf(__ldg(xp + 1), v1,
                 fmaf(__ldg(xp), v0, nb))));
        }
        for (int n = ge; n < end; n++) {
            const float* xp = x + 3 * n;
            proc(fmaf(__ldg(xp + 2), v2, fmaf(__ldg(xp + 1), v1,
                 fmaf(__ldg(xp), v0, nb))));
        }
    }
    __syncthreads();

    // ---- parallel epilogue into scratch: warp w owns bins [bs, be] ----
    // contribution[b-1] = sum_{b'<b} C[b'] + 0.5*(C[b] + Th[b])
    float* sb = g_scratch + seg * (SDIM * TDIM);
    {
        const int bs = (w == 0) ? 0 : 8 * w + 1;
        const int be = 8 * w + 8;                  // inclusive

        float tot = 0.f;
        for (int b = bs; b <= be; b++) {
            int o = b * PITCH + t;
            float2 f0 = __half22float2(acc[0][o]);
            float2 f1 = __half22float2(acc[1][o]);
            float2 f2 = __half22float2(acc[2][o]);
            float2 f3 = __half22float2(acc[3][o]);
            tot += (f0.x + f1.x) + (f2.x + f3.x);
        }
        tw[w][t] = tot;
        __syncthreads();

        float run = 0.f;
        #pragma unroll
        for (int ww = 0; ww < NWARPS; ww++)
            if (ww < w) run += tw[ww][t];
        for (int b = bs; b <= be; b++) {
            int o = b * PITCH + t;
            float2 f0 = __half22float2(acc[0][o]);
            float2 f1 = __half22float2(acc[1][o]);
            float2 f2 = __half22float2(acc[2][o]);
            float2 f3 = __half22float2(acc[3][o]);
            float C  = (f0.x + f1.x) + (f2.x + f3.x);
            float Th = (f0.y + f1.y) + (f2.y + f3.y);
            if (b >= 1) atomicAdd(sb + (b - 1) * TDIM + t, fmaf(0.5f, C + Th, run));
            run += C;
        }
    }

    // ---- last-CTA-per-segment finalization (self-cleaning for graph replay) ----
    __threadfence();
    if (tid == 0) {
        unsigned old = atomicAdd(&g_count[seg], 1u);
        islast = (old == SPLIT - 1);
    }
    __syncthreads();
    if (islast) {
        __threadfence();   // all partners' REDs visible at L2
        float* ob = out + seg * (SDIM * TDIM);
        for (int i = tid; i < SDIM * TDIM; i += NTHREADS) {
            float val = __ldcg(sb + i);            // L2-coherent read
            ob[i] = val;
            sb[i] = 0.f;                           // reset for next replay
        }
        if (tid == 0) g_count[seg] = 0u;           // reset counter
    }
}

extern "C" void kernel_launch(void* const* d_in, const int* in_sizes, int n_in,
                              void* d_out, int out_size)
{
    const float* x     = (const float*)d_in[0];
    const void*  index = d_in[1];
    const float* v     = (const float*)d_in[2];
    const float* lin   = (const float*)d_in[3];
    const void*  scale = d_in[4];
    float*       out   = (float*)d_out;
    const int N = in_sizes[1];

    const int scan_threads = (N + 3) / 4;
    const int prep_blocks  = (scan_threads + 255) / 256;
    prep_kernel<<<prep_blocks, 256>>>(index, N);
    ect_kernel<<<NSEG * SPLIT, NTHREADS>>>(x, v, lin, scale, out);
}

// round 15
// speedup vs baseline: 1.2600x; 1.2600x over previous
#include <cuda_runtime.h>
#include <cuda_fp16.h>

#define NSEG   128
#define SDIM   32
#define TDIM   32
#define NWARPS 4
#define NTHREADS 128
#define SPLIT  12
#define NBINS  34                 // bin = r+1, r in [-1, 32]
#define PITCH  32                 // word addr = 32*bin + t  ->  bank = t (conflict-free)

__device__ int g_bounds[NSEG + 1];

__device__ __forceinline__ long long ld_idx(const void* p, int i, bool is64) {
    return is64 ? ((const long long*)p)[i] : (long long)((const int*)p)[i];
}

// prep: zero output (float4) + segment boundaries via vectorized flat scan
__global__ void __launch_bounds__(256)
prep_kernel(const void* __restrict__ idxraw, float* __restrict__ out,
            int out_n, int N)
{
    const int gtid   = blockIdx.x * blockDim.x + threadIdx.x;
    const int stride = gridDim.x * blockDim.x;

    float4* o4 = (float4*)out;
    for (int i = gtid; i < (out_n >> 2); i += stride)
        o4[i] = make_float4(0.f, 0.f, 0.f, 0.f);

    const bool is64 = (((const int*)idxraw)[(N - 2) | 1] == 0);

    const int base = gtid * 8;
    if (base >= N) return;
    int vals[9];
    if (is64) {
        const longlong2* p = (const longlong2*)idxraw;
        #pragma unroll
        for (int k = 0; k < 4; k++) {
            int ii = (base >> 1) + k;
            if (base + 2 * k < N) {
                longlong2 v2 = __ldg(p + ii);
                vals[2 * k]     = (int)v2.x;
                vals[2 * k + 1] = (int)v2.y;
            }
        }
    } else {
        const int4* p = (const int4*)idxraw;
        #pragma unroll
        for (int k = 0; k < 2; k++) {
            if (base + 4 * k < N) {
                int4 v4 = __ldg(p + (base >> 2) + k);
                vals[4 * k] = v4.x; vals[4 * k + 1] = v4.y;
                vals[4 * k + 2] = v4.z; vals[4 * k + 3] = v4.w;
            }
        }
    }
    vals[8] = (base + 8 < N) ? (int)ld_idx(idxraw, base + 8, is64) : NSEG;

    if (base == 0)
        for (int j = 0; j <= vals[0]; j++) g_bounds[j] = 0;
    #pragma unroll
    for (int k = 0; k < 8; k++) {
        int i = base + k;
        if (i < N) {
            int a = vals[k];
            int b = (i == N - 1) ? NSEG : vals[k + 1];
            for (int j = a + 1; j <= b; j++) g_bounds[j] = i + 1;
        }
    }
}

__global__ void __launch_bounds__(NTHREADS, SPLIT)
ect_kernel(const float* __restrict__ x, const float* __restrict__ v,
           const float* __restrict__ lin, const void* __restrict__ scaleraw,
           float* __restrict__ out)
{
    // per-warp accumulators: half2 {count, tanh-sum} per (bin, t)  (4.25 KB/warp)
    __shared__ __half2 acc[NWARPS][NBINS * PITCH];
    __shared__ float   tw[NWARPS][TDIM];

    const int tid = threadIdx.x;
    const int w   = tid >> 5;
    const int t   = tid & 31;
    const int seg  = (int)blockIdx.x / SPLIT;
    const int part = (int)blockIdx.x - seg * SPLIT;

    // zero accumulators, 16B-vectorized
    {
        int4* z = (int4*)&acc[0][0];
        const int n16 = (NWARPS * NBINS * PITCH) / 4;
        for (int i = tid; i < n16; i += NTHREADS)
            z[i] = make_int4(0, 0, 0, 0);
    }

    const int segS = g_bounds[seg];
    const int segE = g_bounds[seg + 1];

    // scale: int32/int64 low word, or float32
    int s_i = *(const int*)scaleraw;
    const float scale = (s_i > 0 && s_i < 1000000) ? (float)s_i
                                                   : *(const float*)scaleraw;

    const float lin0   = lin[0];
    const float dl     = (lin[SDIM - 1] - lin0) * (1.0f / (SDIM - 1));
    const float inv_dl = 1.0f / dl;
    const float K2     = -0.5f * scale * dl;      // tanh arg scale
    const float nb     = -lin0 * inv_dl;
    const float MAGIC  = 12582912.0f;             // 2^23 + 2^22
    const unsigned MAGICI = 0x4B400000u;
    const float K2M    = K2 * MAGIC;

    // fold inv_dl into the projection: u = x . (v*inv_dl) + nb
    const float v0 = v[t] * inv_dl;
    const float v1 = v[TDIM + t] * inv_dl;
    const float v2 = v[2 * TDIM + t] * inv_dl;

    // bin -> smem byte address in ONE IMAD: off = bits(u+MAGIC)*128 + adj
    const unsigned sbase = (unsigned)__cvta_generic_to_shared(&acc[0][0]);
    const unsigned adj   = sbase + (unsigned)(w * NBINS * PITCH * 4)
                         + (unsigned)(t * 4) + 128u - MAGICI * 128u;  // mod 2^32

    const int chunk = (segE - segS + SPLIT - 1) / SPLIT;
    int start = segS + part * chunk;
    if (start > segE) start = segE;
    int end = start + chunk;
    if (end > segE) end = segE;

    int gs = (start + 3) & ~3;                    // first float4-aligned node
    if (gs > end) gs = end;
    const int ge = gs + ((end - gs) & ~3);

    // per-node: ONE fire-and-forget smem reduction (no load-use chain at all)
    auto proc = [&](float u) {
        u = fminf(fmaxf(u, -0.6f), 32.4f);
        float f = u + MAGIC;                       // rint via magic number
        float t1 = fmaf(f, -K2, K2M);              // = -K2*rint(u)
        float z  = fmaf(u, K2, t1);                // = K2*(u - rint(u))
        float th; asm("tanh.approx.f32 %0, %1;" : "=f"(th) : "f"(z));
        __half2 inc = __floats2half2_rn(1.0f, th); // {count, tanh}
        unsigned incu = *reinterpret_cast<unsigned*>(&inc);
        unsigned off = __float_as_uint(f) * 128u + adj;   // single IMAD
        asm volatile("red.shared.add.noftz.f16x2 [%0], %1;"
                     :: "r"(off), "r"(incu) : "memory");
    };

    // main loop: 4 nodes/iter, 3x float4 broadcast loads
    for (int n = gs + w * 4; n < ge; n += NWARPS * 4) {
        const float4* xp = (const float4*)(x + 3 * n);
        float4 A = __ldg(xp), B = __ldg(xp + 1), C = __ldg(xp + 2);
        float u0 = fmaf(A.z, v2, fmaf(A.y, v1, fmaf(A.x, v0, nb)));
        float u1 = fmaf(B.y, v2, fmaf(B.x, v1, fmaf(A.w, v0, nb)));
        float u2 = fmaf(C.x, v2, fmaf(B.w, v1, fmaf(B.z, v0, nb)));
        float u3 = fmaf(C.w, v2, fmaf(C.z, v1, fmaf(C.y, v0, nb)));
        proc(u0); proc(u1); proc(u2); proc(u3);
    }
    // scalar remainders (<= 3 each side), warp 0
    if (w == 0) {
        for (int n = start; n < gs; n++) {
            const float* xp = x + 3 * n;
            proc(fmaf(__ldg(xp + 2), v2, fmaf(__ldg(xp + 1), v1,
                 fmaf(__ldg(xp), v0, nb))));
        }
        for (int n = ge; n < end; n++) {
            const float* xp = x + 3 * n;
            proc(fmaf(__ldg(xp + 2), v2, fmaf(__ldg(xp + 1), v1,
                 fmaf(__ldg(xp), v0, nb))));
        }
    }
    __syncthreads();

    // ---- parallel epilogue: warp w owns bins [bs, be] of 0..32 ----
    // out[b-1] = sum_{b'<b} C[b'] + 0.5*(C[b] + Th[b])
    {
        const int bs = (w == 0) ? 0 : 8 * w + 1;
        const int be = 8 * w + 8;                  // inclusive

        float tot = 0.f;
        for (int b = bs; b <= be; b++) {
            int o = b * PITCH + t;
            float2 f0 = __half22float2(acc[0][o]);
            float2 f1 = __half22float2(acc[1][o]);
            float2 f2 = __half22float2(acc[2][o]);
            float2 f3 = __half22float2(acc[3][o]);
            tot += (f0.x + f1.x) + (f2.x + f3.x);
        }
        tw[w][t] = tot;
        __syncthreads();

        float run = 0.f;
        #pragma unroll
        for (int ww = 0; ww < NWARPS; ww++)
            if (ww < w) run += tw[ww][t];
        float* ob = out + seg * (SDIM * TDIM) + t;
        for (int b = bs; b <= be; b++) {
            int o = b * PITCH + t;
            float2 f0 = __half22float2(acc[0][o]);
            float2 f1 = __half22float2(acc[1][o]);
            float2 f2 = __half22float2(acc[2][o]);
            float2 f3 = __half22float2(acc[3][o]);
            float C  = (f0.x + f1.x) + (f2.x + f3.x);
            float Th = (f0.y + f1.y) + (f2.y + f3.y);
            if (b >= 1) atomicAdd(ob + (b - 1) * TDIM, fmaf(0.5f, C + Th, run));
            run += C;
        }
    }
}

extern "C" void kernel_launch(void* const* d_in, const int* in_sizes, int n_in,
                              void* d_out, int out_size)
{
    const float* x     = (const float*)d_in[0];
    const void*  index = d_in[1];
    const float* v     = (const float*)d_in[2];
    const float* lin   = (const float*)d_in[3];
    const void*  scale = d_in[4];
    float*       out   = (float*)d_out;
    const int N = in_sizes[1];

    const int scan_threads = (N + 7) / 8;
    int prep_blocks = (scan_threads + 255) / 256;
    if (prep_blocks < 128) prep_blocks = 128;
    prep_kernel<<<prep_blocks, 256>>>(index, out, out_size, N);
    ect_kernel<<<NSEG * SPLIT, NTHREADS>>>(x, v, lin, scale, out);
}

// round 16
// speedup vs baseline: 1.4310x; 1.1358x over previous
#include <cuda_runtime.h>
#include <cuda_fp16.h>

#define NSEG   128
#define SDIM   32
#define TDIM   32
#define NWARPS 4
#define NTHREADS 128
#define SPLIT  10
#define NBINS  34                 // bin = r+1, r in [-1, 32]
#define PITCH  32                 // word addr = 32*bin + t  ->  bank = t (conflict-free)

__device__ int g_bounds[NSEG + 1];

__device__ __forceinline__ long long ld_idx(const void* p, int i, bool is64) {
    return is64 ? ((const long long*)p)[i] : (long long)((const int*)p)[i];
}

// prep: zero output (float4) + segment boundaries via vectorized flat scan
__global__ void __launch_bounds__(256)
prep_kernel(const void* __restrict__ idxraw, float* __restrict__ out,
            int out_n, int N)
{
    const int gtid   = blockIdx.x * blockDim.x + threadIdx.x;
    const int stride = gridDim.x * blockDim.x;

    float4* o4 = (float4*)out;
    for (int i = gtid; i < (out_n >> 2); i += stride)
        o4[i] = make_float4(0.f, 0.f, 0.f, 0.f);

    const bool is64 = (((const int*)idxraw)[(N - 2) | 1] == 0);

    const int base = gtid * 8;
    if (base >= N) return;
    int vals[9];
    if (is64) {
        const longlong2* p = (const longlong2*)idxraw;
        #pragma unroll
        for (int k = 0; k < 4; k++) {
            int ii = (base >> 1) + k;
            if (base + 2 * k < N) {
                longlong2 v2 = __ldg(p + ii);
                vals[2 * k]     = (int)v2.x;
                vals[2 * k + 1] = (int)v2.y;
            }
        }
    } else {
        const int4* p = (const int4*)idxraw;
        #pragma unroll
        for (int k = 0; k < 2; k++) {
            if (base + 4 * k < N) {
                int4 v4 = __ldg(p + (base >> 2) + k);
                vals[4 * k] = v4.x; vals[4 * k + 1] = v4.y;
                vals[4 * k + 2] = v4.z; vals[4 * k + 3] = v4.w;
            }
        }
    }
    vals[8] = (base + 8 < N) ? (int)ld_idx(idxraw, base + 8, is64) : NSEG;

    if (base == 0)
        for (int j = 0; j <= vals[0]; j++) g_bounds[j] = 0;
    #pragma unroll
    for (int k = 0; k < 8; k++) {
        int i = base + k;
        if (i < N) {
            int a = vals[k];
            int b = (i == N - 1) ? NSEG : vals[k + 1];
            for (int j = a + 1; j <= b; j++) g_bounds[j] = i + 1;
        }
    }
}

__global__ void __launch_bounds__(NTHREADS, SPLIT)
ect_kernel(const float* __restrict__ x, const float* __restrict__ v,
           const float* __restrict__ lin, const void* __restrict__ scaleraw,
           float* __restrict__ out)
{
    // per-warp accumulators: half2 {count, tanh-sum} per (bin, t)  (4.25 KB/warp)
    __shared__ __half2 acc[NWARPS][NBINS * PITCH];
    __shared__ float   tw[NWARPS][TDIM];

    const int tid = threadIdx.x;
    const int w   = tid >> 5;
    const int t   = tid & 31;
    const int seg  = (int)blockIdx.x / SPLIT;
    const int part = (int)blockIdx.x - seg * SPLIT;

    // zero accumulators, 16B-vectorized
    {
        int4* z = (int4*)&acc[0][0];
        const int n16 = (NWARPS * NBINS * PITCH) / 4;
        for (int i = tid; i < n16; i += NTHREADS)
            z[i] = make_int4(0, 0, 0, 0);
    }

    const int segS = g_bounds[seg];
    const int segE = g_bounds[seg + 1];

    // scale: int32/int64 low word, or float32
    int s_i = *(const int*)scaleraw;
    const float scale = (s_i > 0 && s_i < 1000000) ? (float)s_i
                                                   : *(const float*)scaleraw;

    const float lin0   = lin[0];
    const float dl     = (lin[SDIM - 1] - lin0) * (1.0f / (SDIM - 1));
    const float inv_dl = 1.0f / dl;
    const float K2     = -0.5f * scale * dl;      // tanh arg scale
    const float nb     = -lin0 * inv_dl;
    const float MAGIC  = 12582912.0f;             // 2^23 + 2^22
    const unsigned MAGICI = 0x4B400000u;
    const float K2M    = K2 * MAGIC;

    // fold inv_dl into the projection: u = x . (v*inv_dl) + nb
    const float v0 = v[t] * inv_dl;
    const float v1 = v[TDIM + t] * inv_dl;
    const float v2 = v[2 * TDIM + t] * inv_dl;

    // bin -> smem byte address in ONE IMAD: off = bits(u+MAGIC)*128 + adj
    const unsigned sbase = (unsigned)__cvta_generic_to_shared(&acc[0][0]);
    const unsigned adj   = sbase + (unsigned)(w * NBINS * PITCH * 4)
                         + (unsigned)(t * 4) + 128u - MAGICI * 128u;  // mod 2^32

    const int chunk = (segE - segS + SPLIT - 1) / SPLIT;
    int start = segS + part * chunk;
    if (start > segE) start = segE;
    int end = start + chunk;
    if (end > segE) end = segE;

    int gs = (start + 3) & ~3;                    // first float4-aligned node
    if (gs > end) gs = end;
    const int ge  = gs + ((end - gs) & ~3);       // 4-aligned end
    const int ge8 = gs + ((ge - gs) & ~7);        // 8-node main region

    // serial per-node RMW (LSU pipelines distinct-addr RMWs)
    auto proc = [&](float u) {
        u = fminf(fmaxf(u, -0.6f), 32.4f);
        float f = u + MAGIC;                       // rint via magic number
        float t1 = fmaf(f, -K2, K2M);              // = -K2*rint(u)
        float z  = fmaf(u, K2, t1);                // = K2*(u - rint(u))
        float th; asm("tanh.approx.f32 %0, %1;" : "=f"(th) : "f"(z));
        __half2 inc = __floats2half2_rn(1.0f, th); // {count, tanh}
        unsigned incu = *reinterpret_cast<unsigned*>(&inc);
        unsigned off = __float_as_uint(f) * 128u + adj;   // single IMAD
        unsigned cur;
        asm volatile("ld.shared.b32 %0, [%1];" : "=r"(cur) : "r"(off));
        __half2 ch = *reinterpret_cast<__half2*>(&cur);
        __half2 ih = *reinterpret_cast<__half2*>(&incu);
        ch = __hadd2(ch, ih);
        unsigned res = *reinterpret_cast<unsigned*>(&ch);
        asm volatile("st.shared.b32 [%0], %1;" :: "r"(off), "r"(res));
    };

    // main loop: 8 nodes/iter, 6x float4 broadcast loads (MLP=6)
    for (int n = gs + w * 8; n < ge8; n += NWARPS * 8) {
        const float4* xp = (const float4*)(x + 3 * n);
        float4 A = __ldg(xp),     B = __ldg(xp + 1), C = __ldg(xp + 2);
        float4 D = __ldg(xp + 3), E = __ldg(xp + 4), F = __ldg(xp + 5);
        float u0 = fmaf(A.z, v2, fmaf(A.y, v1, fmaf(A.x, v0, nb)));
        float u1 = fmaf(B.y, v2, fmaf(B.x, v1, fmaf(A.w, v0, nb)));
        float u2 = fmaf(C.x, v2, fmaf(B.w, v1, fmaf(B.z, v0, nb)));
        float u3 = fmaf(C.w, v2, fmaf(C.z, v1, fmaf(C.y, v0, nb)));
        float u4 = fmaf(D.z, v2, fmaf(D.y, v1, fmaf(D.x, v0, nb)));
        float u5 = fmaf(E.y, v2, fmaf(E.x, v1, fmaf(D.w, v0, nb)));
        float u6 = fmaf(F.x, v2, fmaf(E.w, v1, fmaf(E.z, v0, nb)));
        float u7 = fmaf(F.w, v2, fmaf(F.z, v1, fmaf(F.y, v0, nb)));
        proc(u0); proc(u1); proc(u2); proc(u3);
        proc(u4); proc(u5); proc(u6); proc(u7);
    }
    // 4-node leftover group (at most one), warp 1
    if (w == 1 && ge8 < ge) {
        const float4* xp = (const float4*)(x + 3 * ge8);
        float4 A = __ldg(xp), B = __ldg(xp + 1), C = __ldg(xp + 2);
        float u0 = fmaf(A.z, v2, fmaf(A.y, v1, fmaf(A.x, v0, nb)));
        float u1 = fmaf(B.y, v2, fmaf(B.x, v1, fmaf(A.w, v0, nb)));
        float u2 = fmaf(C.x, v2, fmaf(B.w, v1, fmaf(B.z, v0, nb)));
        float u3 = fmaf(C.w, v2, fmaf(C.z, v1, fmaf(C.y, v0, nb)));
        proc(u0); proc(u1); proc(u2); proc(u3);
    }
    // scalar remainders (<= 3 each side), warp 0
    if (w == 0) {
        for (int n = start; n < gs; n++) {
            const float* xp = x + 3 * n;
            proc(fmaf(__ldg(xp + 2), v2, fmaf(__ldg(xp + 1), v1,
                 fmaf(__ldg(xp), v0, nb))));
        }
        for (int n = ge; n < end; n++) {
            const float* xp = x + 3 * n;
            proc(fmaf(__ldg(xp + 2), v2, fmaf(__ldg(xp + 1), v1,
                 fmaf(__ldg(xp), v0, nb))));
        }
    }
    __syncthreads();

    // ---- parallel epilogue: warp w owns bins [bs, be] of 0..32 ----
    // out[b-1] = sum_{b'<b} C[b'] + 0.5*(C[b] + Th[b])
    {
        const int bs = (w == 0) ? 0 : 8 * w + 1;
        const int be = 8 * w + 8;                  // inclusive

        float tot = 0.f;
        for (int b = bs; b <= be; b++) {
            int o = b * PITCH + t;
            float2 f0 = __half22float2(acc[0][o]);
            float2 f1 = __half22float2(acc[1][o]);
            float2 f2 = __half22float2(acc[2][o]);
            float2 f3 = __half22float2(acc[3][o]);
            tot += (f0.x + f1.x) + (f2.x + f3.x);
        }
        tw[w][t] = tot;
        __syncthreads();

        float run = 0.f;
        #pragma unroll
        for (int ww = 0; ww < NWARPS; ww++)
            if (ww < w) run += tw[ww][t];
        float* ob = out + seg * (SDIM * TDIM) + t;
        for (int b = bs; b <= be; b++) {
            int o = b * PITCH + t;
            float2 f0 = __half22float2(acc[0][o]);
            float2 f1 = __half22float2(acc[1][o]);
            float2 f2 = __half22float2(acc[2][o]);
            float2 f3 = __half22float2(acc[3][o]);
            float C  = (f0.x + f1.x) + (f2.x + f3.x);
            float Th = (f0.y + f1.y) + (f2.y + f3.y);
            if (b >= 1) atomicAdd(ob + (b - 1) * TDIM, fmaf(0.5f, C + Th, run));
            run += C;
        }
    }
}

extern "C" void kernel_launch(void* const* d_in, const int* in_sizes, int n_in,
                              void* d_out, int out_size)
{
    const float* x     = (const float*)d_in[0];
    const void*  index = d_in[1];
    const float* v     = (const float*)d_in[2];
    const float* lin   = (const float*)d_in[3];
    const void*  scale = d_in[4];
    float*       out   = (float*)d_out;
    const int N = in_sizes[1];

    const int scan_threads = (N + 7) / 8;
    int prep_blocks = (scan_threads + 255) / 256;
    if (prep_blocks < 128) prep_blocks = 128;
    prep_kernel<<<prep_blocks, 256>>>(index, out, out_size, N);
    ect_kernel<<<NSEG * SPLIT, NTHREADS>>>(x, v, lin, scale, out);
}

// round 17
// speedup vs baseline: 1.4372x; 1.0043x over previous
#include <cuda_runtime.h>
#include <cuda_fp16.h>

#define NSEG   128
#define SDIM   32
#define TDIM   32
#define NWARPS 4
#define NTHREADS 128
#define SPLIT  12
#define NBINS  34                 // bin = r+1, r in [-1, 32]
#define PITCH  32                 // word addr = 32*bin + t  ->  bank = t (conflict-free)

__device__ int g_bounds[NSEG + 1];

__device__ __forceinline__ long long ld_idx(const void* p, int i, bool is64) {
    return is64 ? ((const long long*)p)[i] : (long long)((const int*)p)[i];
}

// prep: zero output (float4) + segment boundaries via vectorized flat scan.
// Signals dependent launch at the very end (all writes done).
__global__ void __launch_bounds__(256)
prep_kernel(const void* __restrict__ idxraw, float* __restrict__ out,
            int out_n, int N)
{
    const int gtid   = blockIdx.x * blockDim.x + threadIdx.x;
    const int stride = gridDim.x * blockDim.x;

    float4* o4 = (float4*)out;
    for (int i = gtid; i < (out_n >> 2); i += stride)
        o4[i] = make_float4(0.f, 0.f, 0.f, 0.f);

    const bool is64 = (((const int*)idxraw)[(N - 2) | 1] == 0);

    const int base = gtid * 8;
    if (base < N) {
        int vals[9];
        if (is64) {
            const longlong2* p = (const longlong2*)idxraw;
            #pragma unroll
            for (int k = 0; k < 4; k++) {
                int ii = (base >> 1) + k;
                if (base + 2 * k < N) {
                    longlong2 v2 = __ldg(p + ii);
                    vals[2 * k]     = (int)v2.x;
                    vals[2 * k + 1] = (int)v2.y;
                }
            }
        } else {
            const int4* p = (const int4*)idxraw;
            #pragma unroll
            for (int k = 0; k < 2; k++) {
                if (base + 4 * k < N) {
                    int4 v4 = __ldg(p + (base >> 2) + k);
                    vals[4 * k] = v4.x; vals[4 * k + 1] = v4.y;
                    vals[4 * k + 2] = v4.z; vals[4 * k + 3] = v4.w;
                }
            }
        }
        vals[8] = (base + 8 < N) ? (int)ld_idx(idxraw, base + 8, is64) : NSEG;

        if (base == 0)
            for (int j = 0; j <= vals[0]; j++) g_bounds[j] = 0;
        #pragma unroll
        for (int k = 0; k < 8; k++) {
            int i = base + k;
            if (i < N) {
                int a = vals[k];
                int b = (i == N - 1) ? NSEG : vals[k + 1];
                for (int j = a + 1; j <= b; j++) g_bounds[j] = i + 1;
            }
        }
    }

    // PDL: allow the dependent ect kernel to launch; prior writes become
    // visible to it at its griddepcontrol.wait.
    asm volatile("griddepcontrol.launch_dependents;");
}

__global__ void __launch_bounds__(NTHREADS, SPLIT)
ect_kernel(const float* __restrict__ x, const float* __restrict__ v,
           const float* __restrict__ lin, const void* __restrict__ scaleraw,
           float* __restrict__ out)
{
    // per-warp accumulators: half2 {count, tanh-sum} per (bin, t)  (4.25 KB/warp)
    __shared__ __half2 acc[NWARPS][NBINS * PITCH];

    const int tid = threadIdx.x;
    const int w   = tid >> 5;
    const int t   = tid & 31;
    const int seg  = (int)blockIdx.x / SPLIT;
    const int part = (int)blockIdx.x - seg * SPLIT;

    // zero accumulators, 16B-vectorized (overlaps with prep via PDL)
    {
        int4* z = (int4*)&acc[0][0];
        const int n16 = (NWARPS * NBINS * PITCH) / 4;
        for (int i = tid; i < n16; i += NTHREADS)
            z[i] = make_int4(0, 0, 0, 0);
    }

    // scale: int32/int64 low word, or float32   (input buffers: independent of prep)
    int s_i = *(const int*)scaleraw;
    const float scale = (s_i > 0 && s_i < 1000000) ? (float)s_i
                                                   : *(const float*)scaleraw;

    const float lin0   = lin[0];
    const float dl     = (lin[SDIM - 1] - lin0) * (1.0f / (SDIM - 1));
    const float inv_dl = 1.0f / dl;
    const float K2     = -0.5f * scale * dl;      // tanh arg scale
    const float nb     = -lin0 * inv_dl;
    const float MAGIC  = 12582912.0f;             // 2^23 + 2^22
    const unsigned MAGICI = 0x4B400000u;
    const float K2M    = K2 * MAGIC;

    // fold inv_dl into the projection: u = x . (v*inv_dl) + nb
    const float v0 = v[t] * inv_dl;
    const float v1 = v[TDIM + t] * inv_dl;
    const float v2 = v[2 * TDIM + t] * inv_dl;

    // bin -> smem byte address in ONE IMAD: off = bits(u+MAGIC)*128 + adj
    const unsigned sbase = (unsigned)__cvta_generic_to_shared(&acc[0][0]);
    const unsigned adj   = sbase + (unsigned)(w * NBINS * PITCH * 4)
                         + (unsigned)(t * 4) + 128u - MAGICI * 128u;  // mod 2^32

    // PDL: wait for prep's g_bounds + out-zeroing to be complete/visible
    asm volatile("griddepcontrol.wait;" ::: "memory");

    const int segS = g_bounds[seg];
    const int segE = g_bounds[seg + 1];

    const int chunk = (segE - segS + SPLIT - 1) / SPLIT;
    int start = segS + part * chunk;
    if (start > segE) start = segE;
    int end = start + chunk;
    if (end > segE) end = segE;

    int gs = (start + 3) & ~3;                    // first float4-aligned node
    if (gs > end) gs = end;
    const int ge = gs + ((end - gs) & ~3);

    // serial per-node RMW (LSU pipelines distinct-addr RMWs)
    auto proc = [&](float u) {
        u = fminf(fmaxf(u, -0.6f), 32.4f);
        float f = u + MAGIC;                       // rint via magic number
        float t1 = fmaf(f, -K2, K2M);              // = -K2*rint(u)
        float z  = fmaf(u, K2, t1);                // = K2*(u - rint(u))
        float th; asm("tanh.approx.f32 %0, %1;" : "=f"(th) : "f"(z));
        __half2 inc = __floats2half2_rn(1.0f, th); // {count, tanh}
        unsigned incu = *reinterpret_cast<unsigned*>(&inc);
        unsigned off = __float_as_uint(f) * 128u + adj;   // single IMAD
        unsigned cur;
        asm volatile("ld.shared.b32 %0, [%1];" : "=r"(cur) : "r"(off));
        __half2 ch = *reinterpret_cast<__half2*>(&cur);
        __half2 ih = *reinterpret_cast<__half2*>(&incu);
        ch = __hadd2(ch, ih);
        unsigned res = *reinterpret_cast<unsigned*>(&ch);
        asm volatile("st.shared.b32 [%0], %1;" :: "r"(off), "r"(res));
    };

    // main loop: 4 nodes/iter, 3x float4 broadcast loads
    for (int n = gs + w * 4; n < ge; n += NWARPS * 4) {
        const float4* xp = (const float4*)(x + 3 * n);
        float4 A = __ldg(xp), B = __ldg(xp + 1), C = __ldg(xp + 2);
        float u0 = fmaf(A.z, v2, fmaf(A.y, v1, fmaf(A.x, v0, nb)));
        float u1 = fmaf(B.y, v2, fmaf(B.x, v1, fmaf(A.w, v0, nb)));
        float u2 = fmaf(C.x, v2, fmaf(B.w, v1, fmaf(B.z, v0, nb)));
        float u3 = fmaf(C.w, v2, fmaf(C.z, v1, fmaf(C.y, v0, nb)));
        proc(u0); proc(u1); proc(u2); proc(u3);
    }
    // scalar remainders (<= 3 each side), warp 0
    if (w == 0) {
        for (int n = start; n < gs; n++) {
            const float* xp = x + 3 * n;
            proc(fmaf(__ldg(xp + 2), v2, fmaf(__ldg(xp + 1), v1,
                 fmaf(__ldg(xp), v0, nb))));
        }
        for (int n = ge; n < end; n++) {
            const float* xp = x + 3 * n;
            proc(fmaf(__ldg(xp + 2), v2, fmaf(__ldg(xp + 1), v1,
                 fmaf(__ldg(xp), v0, nb))));
        }
    }
    __syncthreads();

    // warp 0: reduce 4 copies + prefix over bins + RED into out
    // out[s] = prefixIncl(C)[s] + 0.5*(C[s+1] + Th[s+1])
    if (w == 0) {
        float run = 0.f;
        float* ob = out + seg * (SDIM * TDIM) + t;
        #pragma unroll
        for (int b = 0; b <= SDIM; b++) {
            int o = b * PITCH + t;
            __half2 h0 = acc[0][o], h1 = acc[1][o], h2 = acc[2][o], h3 = acc[3][o];
            float2 f0 = __half22float2(h0), f1 = __half22float2(h1);
            float2 f2 = __half22float2(h2), f3 = __half22float2(h3);
            float C  = (f0.x + f1.x) + (f2.x + f3.x);
            float Th = (f0.y + f1.y) + (f2.y + f3.y);
            if (b >= 1) atomicAdd(ob + (b - 1) * TDIM, fmaf(0.5f, C + Th, run));
            run += C;
        }
    }
}

extern "C" void kernel_launch(void* const* d_in, const int* in_sizes, int n_in,
                              void* d_out, int out_size)
{
    const float* x     = (const float*)d_in[0];
    const void*  index = d_in[1];
    const float* v     = (const float*)d_in[2];
    const float* lin   = (const float*)d_in[3];
    const void*  scale = d_in[4];
    float*       out   = (float*)d_out;
    const int N = in_sizes[1];

    const int scan_threads = (N + 7) / 8;
    int prep_blocks = (scan_threads + 255) / 256;
    if (prep_blocks < 128) prep_blocks = 128;
    prep_kernel<<<prep_blocks, 256>>>(index, out, out_size, N);

    // ect launched with Programmatic Dependent Launch: it may begin its
    // prologue while prep finishes; griddepcontrol.wait inside provides
    // the ordering on g_bounds / zeroed out.
    {
        cudaLaunchConfig_t cfg = {};
        cfg.gridDim  = dim3(NSEG * SPLIT);
        cfg.blockDim = dim3(NTHREADS);
        cudaLaunchAttribute attr[1];
        attr[0].id = cudaLaunchAttributeProgrammaticStreamSerialization;
        attr[0].val.programmaticStreamSerializationAllowed = 1;
        cfg.attrs    = attr;
        cfg.numAttrs = 1;
        cudaLaunchKernelEx(&cfg, ect_kernel, x, v, lin, scale, out);
    }
}